// round 8
// baseline (speedup 1.0000x reference)
#include <cuda_runtime.h>
#include <math.h>

#define NODES 512
#define S     8
#define DIN   768
#define NN    4096                 /* NODES * S */
#define NB    128                  /* persistent blocks per matrix */
#define TPB   512
#define NWT   (NB * (TPB / 32))    /* warps per matrix = 2048 */

/* Kahan step, rounding-locked (fast-math-proof) */
#define KH(s, c, p) do {                                 \
    float _y = __fsub_rn((p), (c));                      \
    float _t = __fadd_rn((s), _y);                       \
    (c) = __fsub_rn(__fsub_rn(_t, (s)), _y);             \
    (s) = _t;                                            \
} while (0)

/* EFT rank-2 update of one (hi,lo) element + Kahan dot contribution */
#define UPD1(AX, AY, SVT, SWT, SNT, VR, WR, SS, CC) do {               \
    float _dl = __fmaf_rn(-(VR), (SWT), __fmul_rn(-(WR), (SVT)));      \
    float _d2 = __fadd_rn(_dl, (AY));                                  \
    float _hi = __fadd_rn((AX), _d2);                                  \
    float _bp = __fsub_rn(_hi, (AX));                                  \
    float _ap = __fsub_rn(_hi, _bp);                                   \
    float _lo = __fadd_rn(__fsub_rn((AX), _ap), __fsub_rn(_d2, _bp));  \
    (AX) = _hi; (AY) = _lo;                                            \
    float _pp = __fmaf_rn(_lo, (SNT), __fmul_rn(_hi, (SNT)));          \
    KH((SS), (CC), _pp);                                               \
} while (0)

/* ------------------------------------------------------------------ */
/* Static device scratch (no allocations allowed)                      */
/* ------------------------------------------------------------------ */
__device__ float         g_X[2][NODES][S];
__device__ unsigned char g_adj[2][NODES][NODES];
__device__ __align__(16) float2 g_A[2][(size_t)NN * NN];  /* (hi,lo) fp32 */
__device__ float         g_y[2][NN];
__device__ double        g_vty[2][NN];
__device__ double        g_diag[2][NN];
__device__ double        g_offd[2][NN];
__device__ float         g_eig[2][NN];
__device__ unsigned int  g_count[2];
__device__ unsigned int  g_gen[2];

/* ------------------------------------------------------------------ */
/* software grid barrier over NB blocks of one matrix                  */
/* ------------------------------------------------------------------ */
__device__ __forceinline__ void gridbar(int mat)
{
    __threadfence();
    __syncthreads();
    if (threadIdx.x == 0) {
        volatile unsigned int* genp = &g_gen[mat];
        unsigned int old = *genp;
        if (atomicAdd(&g_count[mat], 1u) == (unsigned)(NB - 1)) {
            atomicExch(&g_count[mat], 0u);
            __threadfence();
            atomicExch(&g_gen[mat], old + 1u);
        } else {
            while (*genp == old) __nanosleep(64);
        }
        __threadfence();
    }
    __syncthreads();
}

/* ------------------------------------------------------------------ */
/* K1: X = cloud @ W^T ; zero adjacency                                */
/* ------------------------------------------------------------------ */
__global__ __launch_bounds__(256) void k_proj(const float* __restrict__ q,
                                              const float* __restrict__ pos,
                                              const float* __restrict__ neg,
                                              const float* __restrict__ W)
{
    int b     = blockIdx.x;
    int cloud = b >> 9;
    int row   = b & 511;
    const float* src = (row < 256) ? (q + (size_t)row * DIN)
                                   : ((cloud == 0 ? pos : neg) + (size_t)(row - 256) * DIN);
    __shared__ float sm[256];
    int t = threadIdx.x;
    int c = t & 7;
    int g = t >> 3;
    float acc = 0.f;
    for (int j = g; j < DIN; j += 32)
        acc += src[j] * W[c * DIN + j];
    sm[t] = acc;
    __syncthreads();
    for (int off = 128; off >= 8; off >>= 1) {
        if (t < off) sm[t] += sm[t + off];
        __syncthreads();
    }
    if (t < 8) g_X[cloud][row][t] = sm[t];

    int* adj32 = (int*)g_adj;
    int  base  = b * 128;
    for (int i = t; i < 128; i += 256) adj32[base + i] = 0;
}

/* ------------------------------------------------------------------ */
/* K2: KNN (K=5) + symmetric adjacency                                  */
/* ------------------------------------------------------------------ */
__global__ __launch_bounds__(256) void k_knn()
{
    int b     = blockIdx.x;
    int cloud = b >> 9;
    int i     = b & 511;
    __shared__ float sX[NODES][S];
    __shared__ float sd[NODES];
    int t = threadIdx.x;
    for (int idx = t; idx < NODES * S; idx += 256)
        ((float*)sX)[idx] = ((const float*)g_X[cloud])[idx];
    __syncthreads();
    for (int j = t; j < NODES; j += 256) {
        float d2 = 0.f;
        #pragma unroll
        for (int c = 0; c < S; c++) {
            float d = sX[j][c] - sX[i][c];
            d2 += d * d;
        }
        sd[j] = (j == i) ? 3.4e38f : d2;
    }
    __syncthreads();
    if (t == 0) {
        for (int p = 0; p < 5; p++) {
            float best = 3.4e38f;
            int   bj   = 0;
            for (int j = 0; j < NODES; j++)
                if (sd[j] < best) { best = sd[j]; bj = j; }
            sd[bj] = 3.4e38f;
            g_adj[cloud][i][bj] = 1;
            g_adj[cloud][bj][i] = 1;
        }
    }
}

/* ------------------------------------------------------------------ */
/* K3: assemble dense L into compensated (hi,lo) fp32                   */
/* ------------------------------------------------------------------ */
__global__ __launch_bounds__(256) void k_assemble()
{
    int i     = blockIdx.x;
    int cloud = blockIdx.y;
    __shared__ float         sX[NODES][S];
    __shared__ unsigned char sadj[NODES];
    __shared__ double        sdiag[64];
    int t = threadIdx.x;
    for (int idx = t; idx < NODES * S; idx += 256)
        ((float*)sX)[idx] = ((const float*)g_X[cloud])[idx];
    for (int idx = t; idx < NODES; idx += 256)
        sadj[idx] = g_adj[cloud][i][idx];
    __syncthreads();

    if (t < 64) {
        int    a  = t >> 3, bb = t & 7;
        double acc = 0.0;
        int    deg = 0;
        for (int k = 0; k < NODES; k++) {
            if (!sadj[k]) continue;
            deg++;
            if (k < i) {
                double d[S];
                double dn2 = 0.0;
                #pragma unroll
                for (int c = 0; c < S; c++) {
                    d[c] = (double)sX[i][c] - (double)sX[k][c];
                    dn2 += d[c] * d[c];
                }
                double dn    = sqrt(dn2) + 1e-12;
                double alpha = fmin(dn, 1.0);
                double coef  = (2.0 * alpha - alpha * alpha) / (dn * dn);
                acc -= coef * d[a] * d[bb];
            }
        }
        if (a == bb) acc += (double)deg;
        sdiag[t] = acc;
    }
    __syncthreads();

    int   a    = t >> 5;
    int   lane = t & 31;
    float2* rowp = g_A[cloud] + (size_t)(8 * i + a) * NN;
    for (int cb = 0; cb < NN; cb += 32) {
        int col = cb + lane;
        int j   = col >> 3, bb = col & 7;
        double val = 0.0;
        if (j == i) {
            val = sdiag[a * 8 + bb];
        } else if (sadj[j]) {
            double d[S];
            double dn2 = 0.0;
            #pragma unroll
            for (int c = 0; c < S; c++) {
                d[c] = (double)sX[j][c] - (double)sX[i][c];
                dn2 += d[c] * d[c];
            }
            double dn    = sqrt(dn2) + 1e-12;
            double alpha = fmin(dn, 1.0);
            double sc    = alpha / (dn * dn);
            val = sc * d[a] * d[bb] - (a == bb ? 1.0 : 0.0);
        }
        float hi = (float)val;
        float lo = (float)(val - (double)hi);
        rowp[col] = make_float2(hi, lo);
    }
}

/* ------------------------------------------------------------------ */
/* K4: persistent fused mixed-precision Householder tridiagonalization  */
/* fp32 bulk (EFT storage + Kahan dots), fp64 scalars.                  */
/* Sweep: float4-vectorized, 2 rows/warp, 2 Kahan chains/row.           */
/* ------------------------------------------------------------------ */
__global__ __launch_bounds__(TPB, 2) void k_tridiag()
{
    extern __shared__ float fsm[];
    float* sv  = fsm;             /* v_j                         */
    float* sw  = fsm + NN;        /* w_j                         */
    float* svn = fsm + 2 * NN;    /* virtual row j+1 -> v_{j+1}  */
    __shared__ double sred[TPB / 32];
    __shared__ double s_alpha, s_norm2;

    int mat  = blockIdx.x / NB;
    int blk  = blockIdx.x % NB;
    int tid  = threadIdx.x;
    int lane = tid & 31;
    int wid  = tid >> 5;
    int gw   = blk * (TPB / 32) + wid;
    float2* A = g_A[mat];

    for (int i = blk * TPB + tid; i < NN; i += NB * TPB)
        g_vty[mat][i] = 0.0;
    gridbar(mat);

    /* ---------------- init: reflector 0 ---------------- */
    for (int t = tid; t < NN; t += TPB)
        svn[t] = __fadd_rn(A[t].x, A[t].y);
    __syncthreads();
    {
        double p = 0.0;
        for (int t = tid; t < NN; t += TPB)
            if (t >= 2) p += (double)svn[t] * (double)svn[t];
        #pragma unroll
        for (int o = 16; o; o >>= 1) p += __shfl_xor_sync(~0u, p, o);
        if (lane == 0) sred[wid] = p;
        __syncthreads();
        if (tid == 0) {
            double s = 0.0;
            for (int i = 0; i < TPB / 32; i++) s += sred[i];
            s_norm2 = s;
            s_alpha = (double)svn[1];
            if (blk == 0) g_diag[mat][0] = (double)svn[0];
        }
        __syncthreads();
        double a2  = s_alpha, n22 = s_norm2;
        double sc2 = (n22 == 0.0) ? 0.0
                   : 1.0 / (a2 + copysign(sqrt(a2 * a2 + n22), a2));
        for (int t = tid; t < NN; t += TPB)
            if (t >= 2) svn[t] = (float)((double)svn[t] * sc2);
        if (tid == 0) { svn[1] = 1.0f; svn[0] = 0.0f; }
        __syncthreads();
    }
    /* y_0 = A(1..,1..) * v_0 ; vty_0 */
    {
        double vtyp = 0.0;
        for (int q = 1 + gw; q < NN; q += NWT) {
            const float2* Ar = A + (size_t)q * NN;
            float s = 0.f, cc = 0.f;
            for (int t = lane; t < NN; t += 32) {
                float2 a = Ar[t];
                float  p = __fmaf_rn(a.y, svn[t], __fmul_rn(a.x, svn[t]));
                KH(s, cc, p);
            }
            double y = (double)s + (double)cc;
            #pragma unroll
            for (int o = 16; o; o >>= 1) y += __shfl_xor_sync(~0u, y, o);
            if (lane == 0) {
                g_y[mat][q - 1] = (float)y;
                vtyp += (double)svn[q] * y;
            }
        }
        if (lane == 0) sred[wid] = vtyp;
        __syncthreads();
        if (tid == 0) {
            double s = 0.0;
            for (int i = 0; i < TPB / 32; i++) s += sred[i];
            atomicAdd(&g_vty[mat][0], s);
        }
        __syncthreads();
        for (int t = tid; t < NN - 1; t += TPB) sv[t] = svn[t + 1];
    }
    gridbar(mat);

    /* ---------------- main loop, 1 barrier/step ---------------- */
    for (int j = 0; j + 2 < NN; ++j) {
        int m = NN - 1 - j;

        /* (a) reflector-j scalars in fp64 (identical across blocks) */
        double alpha = s_alpha, n2 = s_norm2;
        double vty = g_vty[mat][j];
        double tau, beta;
        if (n2 == 0.0) { tau = 0.0; beta = alpha; }
        else {
            beta = -copysign(sqrt(alpha * alpha + n2), alpha);
            tau  = (beta - alpha) / beta;
        }
        if (blk == 0 && tid == 0) g_offd[mat][j] = beta;
        double c2 = 0.5 * tau * tau * vty;

        /* (b) w_j = tau*y - c2*v  (fp64 form, fp32 store) */
        const float* yg = g_y[mat];
        for (int t = tid; t < m; t += TPB)
            sw[t] = (float)(tau * (double)yg[t] - c2 * (double)sv[t]);
        __syncthreads();

        /* (c) virtual update of row j+1 */
        {
            const float2* rj1 = A + (size_t)(j + 1) * NN + (j + 1);
            float v0 = sv[0], w0 = sw[0];
            for (int t = tid; t < m; t += TPB) {
                float2 a = rj1[t];
                float  r = __fadd_rn(a.x, a.y);
                svn[t] = __fsub_rn(__fsub_rn(r, __fmul_rn(v0, sw[t])),
                                   __fmul_rn(w0, sv[t]));
            }
        }
        __syncthreads();

        /* (d) reflector-(j+1) scalars from virtual row */
        {
            double p = 0.0;
            for (int t = tid; t < m; t += TPB)
                if (t >= 2) p += (double)svn[t] * (double)svn[t];
            #pragma unroll
            for (int o = 16; o; o >>= 1) p += __shfl_xor_sync(~0u, p, o);
            if (lane == 0) sred[wid] = p;
            __syncthreads();
            if (tid == 0) {
                double s = 0.0;
                for (int i = 0; i < TPB / 32; i++) s += sred[i];
                s_norm2 = s;
                s_alpha = (double)svn[1];
                if (blk == 0) g_diag[mat][j + 1] = (double)svn[0];
            }
            __syncthreads();
        }

        /* (e) v_{j+1} in svn */
        {
            double a2  = s_alpha, n22 = s_norm2;
            double sc2 = (n22 == 0.0) ? 0.0
                       : 1.0 / (a2 + copysign(sqrt(a2 * a2 + n22), a2));
            for (int t = tid; t < m; t += TPB)
                if (t >= 2) svn[t] = (float)((double)svn[t] * sc2);
            if (tid == 0) { svn[1] = 1.0f; svn[0] = 0.0f; }
            __syncthreads();
        }

        /* (f) fused sweep: float4 EFT rank-2 + Kahan dot, 2 rows/warp */
        {
            int  par  = (j + 1) & 1;                 /* row-start parity */
            int  NP   = (m - par) >> 1;              /* # vector pairs   */
            int  rem  = (m - par) & 1;               /* trailing element */
            double vtyp = 0.0;

            int q1 = 1 + gw;
            if (q1 < m) {
                int q2 = q1 + NWT;
                bool r2 = (q2 < m);

                float vr1 = sv[q1], wr1 = sw[q1];
                float2* Ar1 = A + (size_t)(j + 1 + q1) * NN + (j + 1);
                float4* A41 = (float4*)(Ar1 + par);
                float s10 = 0.f, c10 = 0.f, s11 = 0.f, c11 = 0.f;

                if (r2) {
                    float vr2 = sv[q2], wr2 = sw[q2];
                    float2* Ar2 = A + (size_t)(j + 1 + q2) * NN + (j + 1);
                    float4* A42 = (float4*)(Ar2 + par);
                    float s20 = 0.f, c20 = 0.f, s21 = 0.f, c21 = 0.f;

                    if (par && lane == 0) {
                        float2 a = Ar1[0];
                        UPD1(a.x, a.y, sv[0], sw[0], svn[0], vr1, wr1, s10, c10);
                        Ar1[0] = a;
                        float2 b = Ar2[0];
                        UPD1(b.x, b.y, sv[0], sw[0], svn[0], vr2, wr2, s20, c20);
                        Ar2[0] = b;
                    }
                    for (int k = lane; k < NP; k += 32) {
                        int t = par + 2 * k;
                        float svt0 = sv[t],  svt1 = sv[t + 1];
                        float swt0 = sw[t],  swt1 = sw[t + 1];
                        float snt0 = svn[t], snt1 = svn[t + 1];
                        float4 a = A41[k];
                        float4 b = A42[k];
                        UPD1(a.x, a.y, svt0, swt0, snt0, vr1, wr1, s10, c10);
                        UPD1(a.z, a.w, svt1, swt1, snt1, vr1, wr1, s11, c11);
                        UPD1(b.x, b.y, svt0, swt0, snt0, vr2, wr2, s20, c20);
                        UPD1(b.z, b.w, svt1, swt1, snt1, vr2, wr2, s21, c21);
                        A41[k] = a;
                        A42[k] = b;
                    }
                    if (rem && lane == 0) {
                        int t = m - 1;
                        float2 a = Ar1[t];
                        UPD1(a.x, a.y, sv[t], sw[t], svn[t], vr1, wr1, s11, c11);
                        Ar1[t] = a;
                        float2 b = Ar2[t];
                        UPD1(b.x, b.y, sv[t], sw[t], svn[t], vr2, wr2, s21, c21);
                        Ar2[t] = b;
                    }
                    double y2 = ((double)s20 + (double)c20) + ((double)s21 + (double)c21);
                    #pragma unroll
                    for (int o = 16; o; o >>= 1) y2 += __shfl_xor_sync(~0u, y2, o);
                    if (lane == 0) {
                        g_y[mat][q2 - 1] = (float)y2;
                        vtyp += (double)svn[q2] * y2;
                    }
                } else {
                    if (par && lane == 0) {
                        float2 a = Ar1[0];
                        UPD1(a.x, a.y, sv[0], sw[0], svn[0], vr1, wr1, s10, c10);
                        Ar1[0] = a;
                    }
                    #pragma unroll 2
                    for (int k = lane; k < NP; k += 32) {
                        int t = par + 2 * k;
                        float4 a = A41[k];
                        UPD1(a.x, a.y, sv[t],     sw[t],     svn[t],     vr1, wr1, s10, c10);
                        UPD1(a.z, a.w, sv[t + 1], sw[t + 1], svn[t + 1], vr1, wr1, s11, c11);
                        A41[k] = a;
                    }
                    if (rem && lane == 0) {
                        int t = m - 1;
                        float2 a = Ar1[t];
                        UPD1(a.x, a.y, sv[t], sw[t], svn[t], vr1, wr1, s11, c11);
                        Ar1[t] = a;
                    }
                }
                double y1 = ((double)s10 + (double)c10) + ((double)s11 + (double)c11);
                #pragma unroll
                for (int o = 16; o; o >>= 1) y1 += __shfl_xor_sync(~0u, y1, o);
                if (lane == 0) {
                    g_y[mat][q1 - 1] = (float)y1;
                    vtyp += (double)svn[q1] * y1;
                }
            }
            if (lane == 0) sred[wid] = vtyp;
            __syncthreads();
            if (tid == 0) {
                double s = 0.0;
                for (int i = 0; i < TPB / 32; i++) s += sred[i];
                atomicAdd(&g_vty[mat][j + 1], s);
            }
            __syncthreads();
        }

        /* (g) carry v_{j+1} into sv */
        for (int t = tid; t < m - 1; t += TPB) sv[t] = svn[t + 1];
        gridbar(mat);
    }

    /* tail */
    if (blk == 0 && tid == 0) {
        g_offd[mat][NN - 2] = s_alpha;
        g_offd[mat][NN - 1] = 0.0;
        float2 last = A[(size_t)(NN - 1) * NN + (NN - 1)];
        g_diag[mat][NN - 1] = (double)last.x + (double)last.y;
    }
}

/* ------------------------------------------------------------------ */
/* K5: Sturm bisection (fp32), all 4096 eigenvalues per matrix          */
/* ------------------------------------------------------------------ */
__global__ __launch_bounds__(256) void k_bisect()
{
    int mat = blockIdx.y;
    __shared__ float sa[NN];
    __shared__ float sb2[NN];
    __shared__ float red[256];
    __shared__ float s_gl, s_gu, s_pm;
    int t = threadIdx.x;
    for (int i = t; i < NN; i += 256) {
        sa[i] = (float)g_diag[mat][i];
        float b = (i < NN - 1) ? (float)g_offd[mat][i] : 0.f;
        sb2[i] = b * b;
    }
    __syncthreads();

    float lo = 3.4e38f, hi = -3.4e38f, mb2 = 0.f;
    for (int i = t; i < NN; i += 256) {
        float bl = (i > 0)      ? sqrtf(sb2[i - 1]) : 0.f;
        float br = (i < NN - 1) ? sqrtf(sb2[i])     : 0.f;
        lo  = fminf(lo, sa[i] - bl - br);
        hi  = fmaxf(hi, sa[i] + bl + br);
        mb2 = fmaxf(mb2, sb2[i]);
    }
    red[t] = lo;  __syncthreads();
    for (int off = 128; off; off >>= 1) { if (t < off) red[t] = fminf(red[t], red[t + off]); __syncthreads(); }
    if (t == 0) s_gl = red[0];
    __syncthreads();
    red[t] = hi;  __syncthreads();
    for (int off = 128; off; off >>= 1) { if (t < off) red[t] = fmaxf(red[t], red[t + off]); __syncthreads(); }
    if (t == 0) s_gu = red[0];
    __syncthreads();
    red[t] = mb2; __syncthreads();
    for (int off = 128; off; off >>= 1) { if (t < off) red[t] = fmaxf(red[t], red[t + off]); __syncthreads(); }
    if (t == 0) s_pm = red[0];
    __syncthreads();

    float span   = s_gu - s_gl;
    float gl     = s_gl - 0.01f * span - 1e-3f;
    float gu     = s_gu + 0.01f * span + 1e-3f;
    float pivmin = fmaxf(s_pm * 1.2e-38f, 1.2e-38f);

    int tgt = blockIdx.x * 256 + t;
    float blo = gl, bhi = gu;
    for (int it = 0; it < 32; it++) {
        float mid = 0.5f * (blo + bhi);
        if (mid <= blo || mid >= bhi) break;
        float d   = sa[0] - mid;
        int   cnt = (d < 0.f);
        #pragma unroll 8
        for (int i = 1; i < NN; i++) {
            d = (sa[i] - mid) - __fdividef(sb2[i - 1], d);
            if (fabsf(d) < pivmin) d = -pivmin;
            cnt += (d < 0.f);
        }
        if (cnt > tgt) bhi = mid; else blo = mid;
    }
    g_eig[mat][tgt] = 0.5f * (blo + bhi);
}

/* ------------------------------------------------------------------ */
/* K6: spectral gaps -> triplet loss scalar (fp64)                      */
/* ------------------------------------------------------------------ */
__global__ __launch_bounds__(256) void k_final(float* __restrict__ out)
{
    __shared__ double sn[256], sd_[256];
    double gap[2];
    int t = threadIdx.x;
    for (int mat = 0; mat < 2; mat++) {
        double accn = 0.0, accd = 0.0;
        for (int i = t; i < NN; i += 256) {
            double lam = (double)fmaxf(g_eig[mat][i], 0.f);
            double z   = (lam - 1e-4) / 0.01;
            double s   = 1.0 / (1.0 + exp(-z));
            accn += lam * s;
            accd += s;
        }
        sn[t] = accn; sd_[t] = accd;
        __syncthreads();
        for (int off = 128; off; off >>= 1) {
            if (t < off) { sn[t] += sn[t + off]; sd_[t] += sd_[t + off]; }
            __syncthreads();
        }
        gap[mat] = sn[0] / (sd_[0] + 1e-12);
        __syncthreads();
    }
    if (t == 0) {
        double trip = gap[0] - gap[1] + 0.5;
        if (trip < 0.0) trip = 0.0;
        out[0] = (float)(trip + 0.1 * gap[0]);
    }
}

/* ------------------------------------------------------------------ */
extern "C" void kernel_launch(void* const* d_in, const int* in_sizes, int n_in,
                              void* d_out, int out_size)
{
    const float* q   = (const float*)d_in[0];
    const float* pos = (const float*)d_in[1];
    const float* neg = (const float*)d_in[2];
    const float* W   = (const float*)d_in[3];
    (void)in_sizes; (void)n_in; (void)out_size;

    cudaFuncSetAttribute((const void*)k_tridiag,
                         cudaFuncAttributeMaxDynamicSharedMemorySize,
                         (int)(3 * NN * sizeof(float)));

    k_proj<<<1024, 256>>>(q, pos, neg, W);
    k_knn<<<1024, 256>>>();
    {
        dim3 ga(512, 2);
        k_assemble<<<ga, 256>>>();
    }
    k_tridiag<<<2 * NB, TPB, 3 * NN * sizeof(float)>>>();
    {
        dim3 gb(16, 2);
        k_bisect<<<gb, 256>>>();
    }
    k_final<<<1, 256>>>((float*)d_out);
}